// round 14
// baseline (speedup 1.0000x reference)
#include <cuda_runtime.h>
#include <math.h>

// Problem constants (fixed by the dataset): B=256, K=512, D=1024
#define B_SZ 256
#define K_SZ 512
#define D_SZ 1024
#define INV_T (1.0f / 0.07f)

#define K_PER_BLOCK 8                      // 8 warps per block, one k per warp
#define BLOCKS_PER_B (K_SZ / K_PER_BLOCK)  // 64
#define NBLK (B_SZ * BLOCKS_PER_B)         // 16384

// Scratch (no cudaMalloc allowed; zero-initialized)
__device__ float g_fg_per_b[B_SZ];       // exp(fg_logit / T) per sample
__device__ float g_part[NBLK];           // per-block partial sums
__device__ float g_bsum[B_SZ];           // per-sample folded sums
__device__ unsigned g_cnt_b[B_SZ];       // per-sample peer counters (0..63)
__device__ unsigned g_cnt_all;           // finisher counter

// fire-and-forget release reduction: warp can retire immediately (no return)
__device__ __forceinline__ void red_release(unsigned* ctr) {
    asm volatile("red.release.gpu.global.add.u32 [%0], %1;"
                 :: "l"(ctr), "r"(1u) : "memory");
}
__device__ __forceinline__ unsigned acq_rel_add(unsigned* ctr) {
    unsigned r;
    asm volatile("atom.acq_rel.gpu.global.add.u32 %0, [%1], %2;"
                 : "=r"(r) : "l"(ctr), "r"(1u) : "memory");
    return r;
}
__device__ __forceinline__ unsigned load_acquire(const unsigned* p) {
    unsigned r;
    asm volatile("ld.acquire.gpu.global.u32 %0, [%1];" : "=r"(r) : "l"(p) : "memory");
    return r;
}

// ---------------------------------------------------------------------------
// ONE kernel, grid = 16384.
//  - ordinary blocks: publish partial via ST + RED.release (no return: warp
//    retires instantly -> full block churn, streamer at its ~75us floor)
//  - kgrp==63 blocks (scheduled after their sample's peers): warp 0 briefly
//    spin-sleeps for 63 peer arrivals, folds the 64 L2-hot partials
//  - 256th fold (acq_rel election) finishes the loss
// ---------------------------------------------------------------------------
__global__ void __launch_bounds__(256) fused_kernel(
    const float* __restrict__ img,
    const float* __restrict__ fg,
    const float* __restrict__ pro,
    float* __restrict__ out)
{
    __shared__ float4 s_img[256];   // 4 KB: the img row
    __shared__ float  s_ss[8];
    __shared__ float  s_fg[8];
    __shared__ float  s_part[8];

    const int blk  = blockIdx.x;
    const int b    = blk >> 6;          // blk / BLOCKS_PER_B
    const int kgrp = blk & 63;          // blk % BLOCKS_PER_B
    const int t    = threadIdx.x;
    const int w    = t >> 5;
    const int l    = t & 31;

    // ---- load img row into smem + sum of squares ----
    float4 v = ((const float4*)(img + (size_t)b * D_SZ))[t];
    s_img[t] = v;

    float ss = v.x * v.x + v.y * v.y + v.z * v.z + v.w * v.w;
    #pragma unroll
    for (int o = 16; o > 0; o >>= 1)
        ss += __shfl_xor_sync(0xFFFFFFFFu, ss, o);
    if (l == 0) s_ss[w] = ss;
    __syncthreads();

    float tss = 0.f;
    #pragma unroll
    for (int i = 0; i < 8; i++) tss += s_ss[i];
    const float inv = 1.0f / sqrtf(tss);

    // ---- fg dot: only in the first block of each sample ----
    if (kgrp == 0) {
        float4 f = ((const float4*)(fg + (size_t)b * D_SZ))[t];
        float fd = v.x * f.x + v.y * f.y + v.z * f.z + v.w * f.w;
        #pragma unroll
        for (int o = 16; o > 0; o >>= 1)
            fd += __shfl_xor_sync(0xFFFFFFFFu, fd, o);
        if (l == 0) s_fg[w] = fd;
        __syncthreads();
        if (t == 0) {
            float tfd = 0.f;
            #pragma unroll
            for (int i = 0; i < 8; i++) tfd += s_fg[i];
            g_fg_per_b[b] = expf(tfd * inv * INV_T);  // ordered by red.release
        }
    }

    // ---- each warp: one (b,k) dot, pro streamed from DRAM ----
    const int k = (kgrp << 3) + w;
    const float4* p4 = (const float4*)(pro + ((size_t)b * K_SZ + k) * D_SZ);

    float4 p[8];
    #pragma unroll
    for (int j = 0; j < 8; j++)
        p[j] = __ldcs(p4 + j * 32 + l);     // 8 independent streaming LDG.128

    float acc = 0.f;
    #pragma unroll
    for (int j = 0; j < 8; j++) {
        float4 a = s_img[j * 32 + l];
        acc += a.x * p[j].x + a.y * p[j].y + a.z * p[j].z + a.w * p[j].w;
    }

    #pragma unroll
    for (int o = 16; o > 0; o >>= 1)
        acc += __shfl_xor_sync(0xFFFFFFFFu, acc, o);
    if (l == 0) s_part[w] = expf(acc * inv * INV_T);
    __syncthreads();
    // warps 1..7 retire here; warp 0 continues.
    if (w != 0) return;

    float tsum = 0.f;
    #pragma unroll
    for (int i = 0; i < 8; i++) tsum += s_part[i];

    if (kgrp != 63) {
        // ---- ordinary block: fire-and-forget publish, retire at once ----
        if (l == 0) {
            g_part[blk] = tsum;
            red_release(&g_cnt_b[b]);       // no return -> no retire stall
        }
        return;
    }

    // ================== FOLDER (kgrp==63, scheduled last of its sample) ====
    if (l == 0) g_part[blk] = tsum;         // own partial (plain store)
    __syncwarp();

    // wait for the 63 peers (short: peers were scheduled before this block).
    // every lane does its own acquire so each lane's later loads are ordered.
    while (load_acquire(&g_cnt_b[b]) != (unsigned)(BLOCKS_PER_B - 1))
        __nanosleep(32);

    // ---- fold this sample's 64 partials (fixed order) ----
    float a = g_part[(b << 6) + l] + g_part[(b << 6) + 32 + l];
    #pragma unroll
    for (int o = 16; o > 0; o >>= 1)
        a += __shfl_xor_sync(0xFFFFFFFFu, a, o);

    unsigned r2 = 0;
    if (l == 0) {
        g_bsum[b]  = a;
        g_cnt_b[b] = 0;                     // reset for next graph replay
        r2 = acq_rel_add(&g_cnt_all);       // release g_bsum, acquire others'
    }
    r2 = __shfl_sync(0xFFFFFFFFu, r2, 0);
    if (r2 != (unsigned)(B_SZ - 1)) return; // not the global finisher

    (void)load_acquire(&g_cnt_all);         // per-lane acquire for g_bsum/fg
    if (l == 0) g_cnt_all = 0;              // reset for next graph replay

    // ---- finisher: fold 256 b-sums + 256 fg terms (fixed order) ----
    double a2 = 0.0, f2 = 0.0;
    #pragma unroll
    for (int j = 0; j < 8; j++) {           // 8 values per lane
        a2 += (double)g_bsum[j * 32 + l];
        f2 += (double)g_fg_per_b[j * 32 + l];
    }
    #pragma unroll
    for (int o = 16; o > 0; o >>= 1) {
        a2 += __shfl_xor_sync(0xFFFFFFFFu, a2, o);
        f2 += __shfl_xor_sync(0xFFFFFFFFu, f2, o);
    }

    if (l == 0) {
        double pos = a2 / (double)K_SZ;     // sum_b mean_k exp(...)
        double neg = pos + f2;
        out[0] = (float)(-log(pos / neg));
    }
}

// ---------------------------------------------------------------------------
extern "C" void kernel_launch(void* const* d_in, const int* in_sizes, int n_in,
                              void* d_out, int out_size)
{
    const float* img = (const float*)d_in[0];  // bg_img_feature [256,1024]
    const float* fg  = (const float*)d_in[1];  // fg_pro_feature [256,1024]
    const float* pro = (const float*)d_in[2];  // bg_pro_feature [256,512,1024]

    fused_kernel<<<NBLK, 256>>>(img, fg, pro, (float*)d_out);
}

// round 15
// speedup vs baseline: 1.0459x; 1.0459x over previous
#include <cuda_runtime.h>
#include <math.h>

// Problem constants (fixed by the dataset): B=256, K=512, D=1024
#define B_SZ 256
#define K_SZ 512
#define D_SZ 1024
#define INV_T (1.0f / 0.07f)

#define K_PER_BLOCK 8                      // 8 warps per block, one k per warp
#define BLOCKS_PER_B (K_SZ / K_PER_BLOCK)  // 64
#define NBLK (B_SZ * BLOCKS_PER_B)         // 16384

// Scratch (no cudaMalloc allowed; zero-initialized)
__device__ float g_fg_per_b[B_SZ];       // exp(fg_logit / T) per sample
__device__ float g_part[NBLK];           // per-block partial sums
__device__ float g_bsum[B_SZ];           // per-sample folded sums
__device__ unsigned g_cnt_b[B_SZ];       // per-sample arrival counters
__device__ unsigned g_cnt_all;           // finisher counter

__device__ __forceinline__ void release_add(unsigned* ctr) {
    unsigned r;
    asm volatile("atom.release.gpu.global.add.u32 %0, [%1], %2;"
                 : "=r"(r) : "l"(ctr), "r"(1u) : "memory");
}
__device__ __forceinline__ unsigned acq_rel_add(unsigned* ctr) {
    unsigned r;
    asm volatile("atom.acq_rel.gpu.global.add.u32 %0, [%1], %2;"
                 : "=r"(r) : "l"(ctr), "r"(1u) : "memory");
    return r;
}
__device__ __forceinline__ unsigned load_acquire(const unsigned* p) {
    unsigned r;
    asm volatile("ld.acquire.gpu.global.u32 %0, [%1];" : "=r"(r) : "l"(p) : "memory");
    return r;
}

// ---------------------------------------------------------------------------
// Kernel A: R10 streamer with ONE change — the 8 streaming pro loads are
// issued BEFORE the img/smem prologue, so DRAM traffic is in flight while the
// block does its norm reduction + syncthreads (kills the start-up bubble).
// grid = 16384, block = 256
// ---------------------------------------------------------------------------
__global__ void __launch_bounds__(256) fused_kernel(
    const float* __restrict__ img,
    const float* __restrict__ fg,
    const float* __restrict__ pro)
{
    __shared__ float4 s_img[256];   // 4 KB: the img row
    __shared__ float  s_ss[8];
    __shared__ float  s_fg[8];
    __shared__ float  s_part[8];

    const int blk  = blockIdx.x;
    const int b    = blk >> 6;          // blk / BLOCKS_PER_B
    const int kgrp = blk & 63;          // blk % BLOCKS_PER_B
    const int t    = threadIdx.x;
    const int w    = t >> 5;
    const int l    = t & 31;

    // PDL: consumer is gated by data counters; let it launch ASAP.
    if (t == 0)
        asm volatile("griddepcontrol.launch_dependents;");

    // ---- issue the DRAM streaming loads FIRST (8 independent LDG.128) ----
    const int k = (kgrp << 3) + w;
    const float4* p4 = (const float4*)(pro + ((size_t)b * K_SZ + k) * D_SZ);

    float4 p[8];
    #pragma unroll
    for (int j = 0; j < 8; j++)
        p[j] = __ldcs(p4 + j * 32 + l);

    // ---- img row -> smem + sum of squares (overlaps the loads above) ----
    float4 v = ((const float4*)(img + (size_t)b * D_SZ))[t];
    s_img[t] = v;

    float ss = v.x * v.x + v.y * v.y + v.z * v.z + v.w * v.w;
    #pragma unroll
    for (int o = 16; o > 0; o >>= 1)
        ss += __shfl_xor_sync(0xFFFFFFFFu, ss, o);
    if (l == 0) s_ss[w] = ss;
    __syncthreads();

    float tss = 0.f;
    #pragma unroll
    for (int i = 0; i < 8; i++) tss += s_ss[i];
    const float inv = 1.0f / sqrtf(tss);

    // ---- fg dot: only in the first block of each sample ----
    if (kgrp == 0) {
        float4 f = ((const float4*)(fg + (size_t)b * D_SZ))[t];
        float fd = v.x * f.x + v.y * f.y + v.z * f.z + v.w * f.w;
        #pragma unroll
        for (int o = 16; o > 0; o >>= 1)
            fd += __shfl_xor_sync(0xFFFFFFFFu, fd, o);
        if (l == 0) s_fg[w] = fd;
        __syncthreads();
        if (t == 0) {
            float tfd = 0.f;
            #pragma unroll
            for (int i = 0; i < 8; i++) tfd += s_fg[i];
            g_fg_per_b[b] = expf(tfd * inv * INV_T);   // ordered by release below
        }
    }

    // ---- consume the (now landed) pro loads against smem img row ----
    float acc = 0.f;
    #pragma unroll
    for (int j = 0; j < 8; j++) {
        float4 a = s_img[j * 32 + l];
        acc += a.x * p[j].x + a.y * p[j].y + a.z * p[j].z + a.w * p[j].w;
    }

    #pragma unroll
    for (int o = 16; o > 0; o >>= 1)
        acc += __shfl_xor_sync(0xFFFFFFFFu, acc, o);
    if (l == 0) s_part[w] = expf(acc * inv * INV_T);
    __syncthreads();

    if (t == 0) {
        float tsum = 0.f;
        #pragma unroll
        for (int i = 0; i < 8; i++) tsum += s_part[i];
        g_part[blk] = tsum;               // fixed order: deterministic
        release_add(&g_cnt_b[b]);         // publish: partials (+ fg) visible
    }
}

// ---------------------------------------------------------------------------
// Kernel B (identical to R10): 256 one-warp blocks, PDL-launched early,
// gated on per-sample counters (never griddepcontrol.wait).
// grid = 256, block = 32
// ---------------------------------------------------------------------------
__global__ void __launch_bounds__(32) reduce_kernel(float* __restrict__ out)
{
    const int b = blockIdx.x;
    const int l = threadIdx.x;

    while (load_acquire(&g_cnt_b[b]) != (unsigned)BLOCKS_PER_B)
        __nanosleep(128);

    // ---- fold 64 partials (fixed order) ----
    float a = g_part[(b << 6) + l] + g_part[(b << 6) + 32 + l];
    #pragma unroll
    for (int o = 16; o > 0; o >>= 1)
        a += __shfl_xor_sync(0xFFFFFFFFu, a, o);

    __shared__ int s_last;
    if (l == 0) {
        g_bsum[b]  = a;
        g_cnt_b[b] = 0;                        // reset for next graph replay
        unsigned r = acq_rel_add(&g_cnt_all);  // release g_bsum, acquire others
        s_last = (r == (unsigned)(B_SZ - 1));
    }
    __syncwarp();
    int last = __shfl_sync(0xFFFFFFFFu, s_last, 0);
    if (!last) return;

    // ---- finisher: fold 256 b-sums + 256 fg terms (fixed order) ----
    if (l == 0) g_cnt_all = 0;                 // reset for next graph replay

    double a2 = 0.0, f2 = 0.0;
    #pragma unroll
    for (int j = 0; j < 8; j++) {              // 8 values per lane
        a2 += (double)g_bsum[j * 32 + l];
        f2 += (double)g_fg_per_b[j * 32 + l];
    }
    #pragma unroll
    for (int o = 16; o > 0; o >>= 1) {
        a2 += __shfl_xor_sync(0xFFFFFFFFu, a2, o);
        f2 += __shfl_xor_sync(0xFFFFFFFFu, f2, o);
    }

    if (l == 0) {
        double pos = a2 / (double)K_SZ;        // sum_b mean_k exp(...)
        double neg = pos + f2;
        out[0] = (float)(-log(pos / neg));
    }
}

// ---------------------------------------------------------------------------
extern "C" void kernel_launch(void* const* d_in, const int* in_sizes, int n_in,
                              void* d_out, int out_size)
{
    const float* img = (const float*)d_in[0];  // bg_img_feature [256,1024]
    const float* fg  = (const float*)d_in[1];  // fg_pro_feature [256,1024]
    const float* pro = (const float*)d_in[2];  // bg_pro_feature [256,512,1024]

    fused_kernel<<<NBLK, 256>>>(img, fg, pro);

    cudaLaunchConfig_t cfg = {};
    cfg.gridDim  = dim3(B_SZ, 1, 1);
    cfg.blockDim = dim3(32, 1, 1);
    cfg.dynamicSmemBytes = 0;
    cudaLaunchAttribute attrs[1];
    attrs[0].id = cudaLaunchAttributeProgrammaticStreamSerialization;
    attrs[0].val.programmaticStreamSerializationAllowed = 1;
    cfg.attrs = attrs;
    cfg.numAttrs = 1;

    float* out = (float*)d_out;
    cudaLaunchKernelEx(&cfg, reduce_kernel, out);
}